// round 15
// baseline (speedup 1.0000x reference)
#include <cuda_runtime.h>
#include <cuda_fp16.h>
#include <math.h>

#define N_MAX 100000
#define E_MAX 1600000
#define HID 128
#define EPSBN 1e-5f

// ---------------- scratch (device globals; no allocation) ----------------
__device__ float g_bufA[N_MAX * HID];
__device__ float g_bufB[N_MAX * HID];
__device__ __half g_h16[N_MAX * HID];   // fp16 shadow of current h, for gathers
__device__ float g_dinv[N_MAX];
__device__ int   g_cnt[N_MAX];
__device__ int   g_rowptr[N_MAX + 1];
__device__ int   g_rank[E_MAX];
__device__ int   g_csr_src[E_MAX];
__device__ float g_csr_ws[E_MAX];     // dinv[src] per edge
__device__ float g_colsum[512];       // 4 slices of 128 (layers 0..2, head)
__device__ float g_colsq[512];
__device__ float g_f[N_MAX * 32];

__device__ __forceinline__ float* selbuf(int s) { return s ? g_bufB : g_bufA; }

__device__ __forceinline__ void h16_unpack(uint2 v, float2& f0, float2& f1) {
    f0 = __half22float2(*(__half2*)&v.x);
    f1 = __half22float2(*(__half2*)&v.y);
}

// ---------------- init: zero counts + all BN stat slices ----------------
__global__ void init_kernel(int n) {
    int i = blockIdx.x * blockDim.x + threadIdx.x;
    if (i < n) g_cnt[i] = 0;
    if (i < 512) { g_colsum[i] = 0.0f; g_colsq[i] = 0.0f; }
}

// ---------------- count + per-edge rank ----------------
__global__ void count_rank_kernel(const int* __restrict__ ei, int e) {
    int i = blockIdx.x * blockDim.x + threadIdx.x;
    if (i < e) {
        int dst = ei[e + i];
        g_rank[i] = atomicAdd(&g_cnt[dst], 1);
    }
}

// ---------------- exclusive scan (1024 threads, shfl-based) + dinv ----------------
__global__ void scan_kernel(int n) {
    __shared__ int wsum[32];
    int tid = threadIdx.x;
    int lane = tid & 31, wid = tid >> 5;
    int chunk = (n + 1023) >> 10;
    int start = tid * chunk;
    int end = start + chunk; if (end > n) end = n;
    int s = 0;
    for (int i = start; i < end; i++) s += g_cnt[i];

    unsigned full = 0xffffffffu;
    int v = s;
#pragma unroll
    for (int o = 1; o < 32; o <<= 1) {
        int t = __shfl_up_sync(full, v, o);
        if (lane >= o) v += t;
    }
    if (lane == 31) wsum[wid] = v;
    __syncthreads();
    if (wid == 0) {
        int w = wsum[lane];
#pragma unroll
        for (int o = 1; o < 32; o <<= 1) {
            int t = __shfl_up_sync(full, w, o);
            if (lane >= o) w += t;
        }
        wsum[lane] = w;
    }
    __syncthreads();
    int base = (wid > 0) ? wsum[wid - 1] : 0;
    int acc = base + v - s;   // exclusive prefix for this thread's chunk
    for (int i = start; i < end; i++) {
        g_rowptr[i] = acc;
        int c = g_cnt[i];
        acc += c;
        g_dinv[i] = rsqrtf((float)c + 1.0f);   // +1 self-loop
    }
    if (tid == 1023) g_rowptr[n] = base + v;
}

// ---------------- fill (atomic-free via rank) ----------------
__global__ void fill_kernel(const int* __restrict__ ei, int e) {
    int i = blockIdx.x * blockDim.x + threadIdx.x;
    if (i < e) {
        int src = ei[i];
        int dst = ei[e + i];
        int idx = g_rowptr[dst] + g_rank[i];
        g_csr_src[idx] = src;
        g_csr_ws[idx] = g_dinv[src];
    }
}

// ---------------- encoder: h = relu(x @ We + be), x[N,2]; writes fp32 + fp16 ----------
__global__ void encoder_kernel(const float* __restrict__ x, const float* __restrict__ We,
                               const float* __restrict__ be, int out_sel, int n) {
    int i = blockIdx.x;
    int j = threadIdx.x;
    if (i >= n) return;
    float v = x[2 * i] * We[j] + x[2 * i + 1] * We[HID + j] + be[j];
    v = fmaxf(v, 0.0f);
    selbuf(out_sel)[i * HID + j] = v;
    g_h16[i * HID + j] = __float2half(v);
}

// ---------------- fused: C = Agg(h16) @ W, plus BN column stats ----------------
// 256 threads, tile 64 rows x 128 cols, micro 8x4 (R5 scalar GEMM — proven).
// Gathers read the fp16 shadow: 256 B/edge instead of 512 B.
__global__ __launch_bounds__(256, 2)
void agg_gemm_kernel(const float* __restrict__ W, int c_sel, int layer, int n) {
    __shared__ float As[64][HID];     // 32 KB
    __shared__ float Bs[32][HID];     // 16 KB
    float* C = selbuf(c_sel);
    const uint2* t2 = (const uint2*)g_h16;   // 32 uint2 per row (128 halves)
    int tid = threadIdx.x;
    int lane = tid & 31, warp = tid >> 5;
    int row0 = blockIdx.x * 64;

    // ---- phase A: aggregate 64 rows into As (warp per node, 8 nodes per warp) ----
#pragma unroll
    for (int r8 = 0; r8 < 8; r8++) {
        int r = warp * 8 + r8;
        int node = row0 + r;
        float4 acc = make_float4(0.f, 0.f, 0.f, 0.f);
        if (node < n) {
            float di = g_dinv[node];
            float2 f0, f1;
            h16_unpack(t2[node * 32 + lane], f0, f1);
            acc.x = di * f0.x; acc.y = di * f0.y; acc.z = di * f1.x; acc.w = di * f1.y;
            int e = g_rowptr[node];
            int end = g_rowptr[node + 1];
            for (; e + 4 <= end; e += 4) {
                int s0 = g_csr_src[e], s1 = g_csr_src[e + 1];
                int s2 = g_csr_src[e + 2], s3 = g_csr_src[e + 3];
                float w0 = g_csr_ws[e], w1 = g_csr_ws[e + 1];
                float w2 = g_csr_ws[e + 2], w3 = g_csr_ws[e + 3];
                uint2 v0 = t2[s0 * 32 + lane];
                uint2 v1 = t2[s1 * 32 + lane];
                uint2 v2 = t2[s2 * 32 + lane];
                uint2 v3 = t2[s3 * 32 + lane];
                float2 a0, b0, a1, b1, a2, b2, a3, b3;
                h16_unpack(v0, a0, b0);
                h16_unpack(v1, a1, b1);
                h16_unpack(v2, a2, b2);
                h16_unpack(v3, a3, b3);
                acc.x += w0 * a0.x + w1 * a1.x + w2 * a2.x + w3 * a3.x;
                acc.y += w0 * a0.y + w1 * a1.y + w2 * a2.y + w3 * a3.y;
                acc.z += w0 * b0.x + w1 * b1.x + w2 * b2.x + w3 * b3.x;
                acc.w += w0 * b0.y + w1 * b1.y + w2 * b2.y + w3 * b3.y;
            }
            for (; e < end; e++) {
                int s = g_csr_src[e];
                float w = g_csr_ws[e];
                float2 a, b;
                h16_unpack(t2[s * 32 + lane], a, b);
                acc.x += w * a.x; acc.y += w * a.y; acc.z += w * b.x; acc.w += w * b.y;
            }
            acc.x *= di; acc.y *= di; acc.z *= di; acc.w *= di;
        }
        *(float4*)&As[r][lane * 4] = acc;
    }

    // ---- phase B: GEMM (R5 scalar), k in 4 chunks of 32 ----
    int tx = lane, ty = warp;
    float acc2[8][4];
#pragma unroll
    for (int i = 0; i < 8; i++)
#pragma unroll
        for (int j = 0; j < 4; j++) acc2[i][j] = 0.0f;

    for (int kc = 0; kc < 4; kc++) {
        __syncthreads();
        {
            const float4* Wv = (const float4*)(W + kc * 32 * HID);
            float4* Bv = (float4*)Bs;
            for (int i = tid; i < 32 * 32; i += 256) Bv[i] = Wv[i];
        }
        __syncthreads();
#pragma unroll
        for (int k = 0; k < 32; k++) {
            float4 b = *(const float4*)&Bs[k][tx * 4];
#pragma unroll
            for (int i = 0; i < 8; i++) {
                float a = As[ty * 8 + i][kc * 32 + k];
                acc2[i][0] += a * b.x;
                acc2[i][1] += a * b.y;
                acc2[i][2] += a * b.z;
                acc2[i][3] += a * b.w;
            }
        }
    }

    // ---- epilogue: write C + BN stats (rows >= n contribute exact zeros) ----
    float ps[4] = {0.f, 0.f, 0.f, 0.f};
    float pq[4] = {0.f, 0.f, 0.f, 0.f};
#pragma unroll
    for (int i = 0; i < 8; i++) {
        int row = row0 + ty * 8 + i;
        if (row < n) {
            *(float4*)&C[row * HID + tx * 4] =
                make_float4(acc2[i][0], acc2[i][1], acc2[i][2], acc2[i][3]);
        }
#pragma unroll
        for (int j = 0; j < 4; j++) {
            ps[j] += acc2[i][j];
            pq[j] += acc2[i][j] * acc2[i][j];
        }
    }
    __syncthreads();                // done with Bs; reuse as 256-float reducer
    float* sc = (float*)Bs;
    sc[tid] = 0.0f;
    __syncthreads();
#pragma unroll
    for (int j = 0; j < 4; j++) {
        atomicAdd(&sc[tx * 4 + j], ps[j]);
        atomicAdd(&sc[128 + tx * 4 + j], pq[j]);
    }
    __syncthreads();
    if (tid < 128) {
        atomicAdd(&g_colsum[layer * 128 + tid], sc[tid]);
        atomicAdd(&g_colsq[layer * 128 + tid], sc[128 + tid]);
    }
}

// ---------------- bnapply: c = relu(bn(c)) + h  (in place), also refresh h16 --------
__global__ void bnapply_kernel(int c_sel, int h_sel, const float* __restrict__ g,
                               const float* __restrict__ bt, int layer, int n) {
    __shared__ float sscale[HID], sshift[HID];
    int tid = threadIdx.x;
    if (tid < HID) {
        float inv_n = 1.0f / (float)n;
        float mu = g_colsum[layer * 128 + tid] * inv_n;
        float var = g_colsq[layer * 128 + tid] * inv_n - mu * mu;
        float sc = rsqrtf(var + EPSBN) * g[tid];
        sscale[tid] = sc;
        sshift[tid] = bt[tid] - mu * sc;
    }
    __syncthreads();
    float4* c4 = (float4*)selbuf(c_sel);
    const float4* h4 = (const float4*)selbuf(h_sel);
    uint2* o16 = (uint2*)g_h16;
    int total = n * 32;
    for (int idx = blockIdx.x * blockDim.x + tid; idx < total; idx += gridDim.x * blockDim.x) {
        int j4 = (idx & 31) * 4;
        float4 c = c4[idx];
        float4 h = h4[idx];
        c.x = fmaxf(c.x * sscale[j4]     + sshift[j4],     0.f) + h.x;
        c.y = fmaxf(c.y * sscale[j4 + 1] + sshift[j4 + 1], 0.f) + h.y;
        c.z = fmaxf(c.z * sscale[j4 + 2] + sshift[j4 + 2], 0.f) + h.z;
        c.w = fmaxf(c.w * sscale[j4 + 3] + sshift[j4 + 3], 0.f) + h.w;
        c4[idx] = c;
        __half2 p0 = __floats2half2_rn(c.x, c.y);
        __half2 p1 = __floats2half2_rn(c.z, c.w);
        uint2 o;
        o.x = *(unsigned*)&p0;
        o.y = *(unsigned*)&p1;
        o16[idx] = o;
    }
}

// ---------------- head: h3 = relu(bn3(C3)) + h2 on the fly; f = h3 @ Wf1 ----------
__global__ __launch_bounds__(256)
void head_kernel(int v_sel, int hold_sel, const float* __restrict__ g3,
                 const float* __restrict__ bt3, const float* __restrict__ Wf1, int n) {
    __shared__ float Ws[HID * 32];
    __shared__ float sscale[HID], sshift[HID];
    __shared__ float sstat[64];
    int tid = threadIdx.x, lane = tid & 31;
    for (int i = tid; i < HID * 32; i += 256) Ws[i] = Wf1[i];
    if (tid < HID) {
        float inv_n = 1.0f / (float)n;
        float mu = g_colsum[256 + tid] * inv_n;
        float var = g_colsq[256 + tid] * inv_n - mu * mu;
        float sc = rsqrtf(var + EPSBN) * g3[tid];
        sscale[tid] = sc;
        sshift[tid] = bt3[tid] - mu * sc;
    }
    if (tid < 64) sstat[tid] = 0.0f;
    __syncthreads();

    const float4* v4 = (const float4*)selbuf(v_sel);
    const float4* h4 = (const float4*)selbuf(hold_sel);
    float s0 = sscale[lane * 4], s1 = sscale[lane * 4 + 1];
    float s2 = sscale[lane * 4 + 2], s3 = sscale[lane * 4 + 3];
    float t0 = sshift[lane * 4], t1 = sshift[lane * 4 + 1];
    float t2 = sshift[lane * 4 + 2], t3 = sshift[lane * 4 + 3];

    int warp_g = (blockIdx.x * 256 + tid) >> 5;
    int nw = (gridDim.x * 256) >> 5;
    float fs = 0.f, fq = 0.f;
    for (int row = warp_g; row < n; row += nw) {
        float4 c = v4[row * 32 + lane];
        float4 h = h4[row * 32 + lane];
        float x0 = fmaxf(c.x * s0 + t0, 0.f) + h.x;
        float x1 = fmaxf(c.y * s1 + t1, 0.f) + h.y;
        float x2 = fmaxf(c.z * s2 + t2, 0.f) + h.z;
        float x3 = fmaxf(c.w * s3 + t3, 0.f) + h.w;
        float acc = 0.0f;
#pragma unroll
        for (int k = 0; k < HID; k++) {
            float comp = ((k & 3) == 0) ? x0 : ((k & 3) == 1) ? x1
                       : ((k & 3) == 2) ? x2 : x3;
            float hk = __shfl_sync(0xffffffffu, comp, k >> 2);
            acc += hk * Ws[k * 32 + lane];
        }
        g_f[row * 32 + lane] = acc;
        fs += acc; fq += acc * acc;
    }
    atomicAdd(&sstat[lane], fs);
    atomicAdd(&sstat[32 + lane], fq);
    __syncthreads();
    if (tid < 32) {
        atomicAdd(&g_colsum[384 + tid], sstat[tid]);
        atomicAdd(&g_colsq[384 + tid], sstat[32 + tid]);
    }
}

// ---------------- final: out = tanh(relu(bn(f)) @ Wf2 + bf2) ----------------
__global__ void final_kernel(const float* __restrict__ gf, const float* __restrict__ btf,
                             const float* __restrict__ Wf2, const float* __restrict__ bf2,
                             float* __restrict__ out, int n) {
    __shared__ float sscale[32], sshift[32], sW[64], sb[2];
    int tid = threadIdx.x;
    if (tid < 32) {
        float inv_n = 1.0f / (float)n;
        float mu = g_colsum[384 + tid] * inv_n;
        float var = g_colsq[384 + tid] * inv_n - mu * mu;
        float sc = rsqrtf(var + EPSBN) * gf[tid];
        sscale[tid] = sc;
        sshift[tid] = btf[tid] - mu * sc;
    }
    if (tid < 64) sW[tid] = Wf2[tid];
    if (tid < 2) sb[tid] = bf2[tid];
    __syncthreads();
    int i = blockIdx.x * blockDim.x + tid;
    if (i >= n) return;
    const float* f = g_f + i * 32;
    float a0 = sb[0], a1 = sb[1];
#pragma unroll
    for (int k = 0; k < 32; k++) {
        float x = fmaxf(f[k] * sscale[k] + sshift[k], 0.f);
        a0 += x * sW[2 * k];
        a1 += x * sW[2 * k + 1];
    }
    out[2 * i] = tanhf(a0);
    out[2 * i + 1] = tanhf(a1);
}

// ---------------- launch ----------------
extern "C" void kernel_launch(void* const* d_in, const int* in_sizes, int n_in,
                              void* d_out, int out_size) {
    const float* x   = (const float*)d_in[0];
    const int*   ei  = (const int*)d_in[1];
    const float* We  = (const float*)d_in[2];
    const float* be  = (const float*)d_in[3];
    const float* W[3]  = {(const float*)d_in[4], (const float*)d_in[8],  (const float*)d_in[12]};
    const float* g[3]  = {(const float*)d_in[6], (const float*)d_in[10], (const float*)d_in[14]};
    const float* bt[3] = {(const float*)d_in[7], (const float*)d_in[11], (const float*)d_in[15]};
    const float* Wf1 = (const float*)d_in[16];
    const float* gf  = (const float*)d_in[18];
    const float* btf = (const float*)d_in[19];
    const float* Wf2 = (const float*)d_in[20];
    const float* bf2 = (const float*)d_in[21];
    float* out = (float*)d_out;

    int n = in_sizes[0] / 2;
    int e = in_sizes[1] / 2;

    // CSR build (rank-based, atomic-free fill)
    init_kernel<<<(n + 255) / 256, 256>>>(n);
    count_rank_kernel<<<(e + 255) / 256, 256>>>(ei, e);
    scan_kernel<<<1, 1024>>>(n);
    fill_kernel<<<(e + 255) / 256, 256>>>(ei, e);

    // encoder -> bufA (+ h16 shadow)
    encoder_kernel<<<n, HID>>>(x, We, be, 0, n);

    // layers: h/c ping-pong between bufA(0) / bufB(1); gathers always read g_h16
    int h_sel = 0, c_sel = 1;
    for (int l = 0; l < 3; l++) {
        agg_gemm_kernel<<<(n + 63) / 64, 256>>>(W[l], c_sel, l, n);
        if (l < 2) {
            bnapply_kernel<<<2048, 256>>>(c_sel, h_sel, g[l], bt[l], l, n);
            int t = h_sel; h_sel = c_sel; c_sel = t;
        }
    }
    // after loop: c_sel holds raw C3 (pre-BN), h_sel holds h2

    head_kernel<<<1536, 256>>>(c_sel, h_sel, g[2], bt[2], Wf1, n);
    final_kernel<<<(n + 255) / 256, 256>>>(gf, btf, Wf2, bf2, out, n);
}